// round 8
// baseline (speedup 1.0000x reference)
#include <cuda_runtime.h>
#include <cstdint>

// MinimalRSNN: GLIF3 + AlphaPSC recurrent SNN — fully fused persistent kernel.
//   Each of 128 CTAs owns 8 h-neurons x all 32 batches.
//   Per step t:  rec GEMM from spikes(t-1) [R4-exact inner loop]
//                -> GLIF3 neuron update (uses I_ext(t) computed last step)
//                -> barrier arrive -> compute I_ext(t+1) slice (hides barrier)
//                -> barrier poll.
//   I_ext(t+1) = x(t+1) @ W_in^T slice: sequential-k single-accumulator fp32
//   (bit-identical ordering to the previously passing standalone SGEMM).
//   x tiles double-buffered into smem via cp.async issued one step early.

#define T_STEPS 1000
#define BATCH   32
#define NI      512
#define NH      1024
#define NO      256

#define V_TH   (-45.0f)
#define V_RST  (-60.0f)
#define D_SYN  0.8187307530779818f
#define D_A0   0.9048374180359595f
#define D_A1   0.8187307530779818f

#define NBLK   128

#define FMA2(d, a, b)  asm("fma.rn.f32x2 %0, %1, %2, %0;" : "+l"(d) : "l"(a), "l"(b))
#define PACK2(d, lo, hi) asm("mov.b64 %0, {%1, %2};" : "=l"(d) : "r"(lo), "r"(hi))
#define UNPK2(lo, hi, s) asm("mov.b64 {%0, %1}, %2;" : "=r"(lo), "=r"(hi) : "l"(s))

typedef unsigned long long u64;
typedef unsigned int       u32;

// -------- device scratch (no allocations allowed) --------
__device__ unsigned short g_spk16[2][BATCH * NH];   // bf16 spikes, double-buffered
__device__ float          g_rate[BATCH * NH];
__device__ unsigned int   g_bar;

__global__ void init_kernel() { if (threadIdx.x == 0) g_bar = 0u; }

// -------- smem layout (floats) --------
//   wt   [0,      8192)   W_rec slice 8x1024
//   winp [8192,  12320)   W_in  slice 8x(512+4 pad)
//   xs   [12320, 45344)   x double buffer: 2 x 32 x (512+4 pad)
#define WT_OFF   0
#define WIN_OFF  8192
#define XROW     516
#define XS_OFF   12320
#define XBUF     (BATCH * XROW)
#define SMEM_FLOATS (XS_OFF + 2 * XBUF)
#define SMEM_BYTES  (SMEM_FLOATS * 4)

__device__ __forceinline__ u32 smem_u32(const void* p) {
    u32 a;
    asm("{ .reg .u64 t; cvta.to.shared.u64 t, %1; cvt.u32.u64 %0, t; }" : "=r"(a) : "l"(p));
    return a;
}
__device__ __forceinline__ void cp16(u32 saddr, const void* gptr) {
    asm volatile("cp.async.cg.shared.global [%0], [%1], 16;" :: "r"(saddr), "l"(gptr));
}
#define CP_COMMIT() asm volatile("cp.async.commit_group;" ::: "memory")
#define CP_WAIT(n)  asm volatile("cp.async.wait_group %0;" :: "n"(n) : "memory")

#define RSTAGE(M, NHALF)                                                        \
    if (ln & (M)) {                                                             \
        _Pragma("unroll")                                                       \
        for (int i = 0; i < (NHALF); i++) {                                     \
            float tmp = a[i]; a[i] = a[i + (NHALF)]; a[i + (NHALF)] = tmp;      \
        }                                                                       \
    }                                                                           \
    _Pragma("unroll")                                                           \
    for (int i = 0; i < (NHALF); i++)                                           \
        a[i] += __shfl_xor_sync(0xffffffffu, a[i + (NHALF)], (M));

// -------- fused persistent scan --------
__global__ __launch_bounds__(256, 1) void scan_kernel(const float* __restrict__ x,
                                                      const float* __restrict__ Win,
                                                      const float* __restrict__ Wrec) {
    extern __shared__ float sm[];
    float* wt   = sm + WT_OFF;
    float* winp = sm + WIN_OFF;
    float* xs   = sm + XS_OFF;
    const u32 xs_base = smem_u32(xs);

    const int tid = threadIdx.x;
    const int w  = tid >> 5;
    const int ln = tid & 31;
    const int c  = blockIdx.x;
    const int h0 = c * 8;
    const int bg = w >> 1;
    const int hg = w & 1;

    // ---- preload W_rec slice (contiguous rows) ----
    {
        const float4* src = (const float4*)(Wrec + (size_t)h0 * NH);
#pragma unroll
        for (int i = 0; i < 8; i++)
            ((float4*)wt)[tid + i * 256] = src[tid + i * 256];
    }
    // ---- preload W_in slice into padded rows ----
    {
#pragma unroll
        for (int i = 0; i < 4; i++) {
            int q = tid + i * 256;            // float4 id: row = q>>7, col4 = q&127
            int row = q >> 7, c4 = q & 127;
            float4 v = ((const float4*)(Win + (size_t)(h0 + row) * NI))[c4];
            *(float4*)&winp[row * XROW + c4 * 4] = v;
        }
    }

    // stage x(t) tile -> xs buffer (t&1). 4096 16B chunks, 16 per thread.
    auto stage_x = [&](int t) {
        const float* src = x + (size_t)t * BATCH * NI;
        u32 dst = xs_base + (u32)((t & 1) * XBUF * 4);
#pragma unroll
        for (int i = 0; i < 16; i++) {
            int j = tid + i * 256;            // 0..4095
            int b = j >> 7, c16 = j & 127;
            cp16(dst + (u32)(b * XROW + c16 * 4) * 4, src + b * NI + c16 * 4);
        }
        CP_COMMIT();
    };

    // neuron ownership (R4 mapping)
    const int b = 8 * bg + (ln >> 2);
    const int h = h0 + 4 * hg + (ln & 3);
    const float* wbase = wt + (4 * hg) * NH + 4 * ln;
    const float* wirow = winp + (4 * hg + (ln & 3)) * XROW;

    // ---- prologue: x(0) -> buf0, compute Iv(0); then stage x(1) ----
    stage_x(0);
    CP_WAIT(0);
    __syncthreads();

    float Iv;
    {
        const float* xr = xs + (0 & 1) * XBUF + b * XROW;
        float acc = 0.f;
#pragma unroll 8
        for (int k4 = 0; k4 < NI / 4; k4++) {
            float4 xv = *(const float4*)(xr + k4 * 4);
            float4 wv = *(const float4*)(wirow + k4 * 4);
            acc += xv.x * wv.x;
            acc += xv.y * wv.y;
            acc += xv.z * wv.z;
            acc += xv.w * wv.w;
        }
        Iv = acc;
    }
    stage_x(1);

    float v = V_RST, a0 = 0.f, a1 = 0.f, ref = 0.f, hs = 0.f, psc = 0.f;
    int cnt = 0;

    for (int t = 0; t < T_STEPS; t++) {
        const bool more = (t + 2 < T_STEPS);
        if (more) stage_x(t + 2);            // lands next step

        // ---- recurrent GEMM from spikes(t-1): R4-exact inner loop ----
        if (t > 0) {
            const char* sp = (const char*)g_spk16[(t - 1) & 1];
            u64 acc[32];
#pragma unroll
            for (int i = 0; i < 32; i++) acc[i] = 0ull;

            uint2 s[8], sn[8];
#pragma unroll
            for (int bb = 0; bb < 8; bb++)
                s[bb] = __ldcg((const uint2*)(sp + (8 * bg + bb) * (NH * 2) + 8 * ln));

#pragma unroll
            for (int u = 0; u < 8; u++) {
                if (u < 7) {
#pragma unroll
                    for (int bb = 0; bb < 8; bb++)
                        sn[bb] = __ldcg((const uint2*)(sp + (8 * bg + bb) * (NH * 2)
                                                          + 8 * ln + 256 * (u + 1)));
                }
                u64 p0[8], p1[8];
#pragma unroll
                for (int bb = 0; bb < 8; bb++) {
                    PACK2(p0[bb], s[bb].x << 16, s[bb].x & 0xFFFF0000u);
                    PACK2(p1[bb], s[bb].y << 16, s[bb].y & 0xFFFF0000u);
                }
#pragma unroll
                for (int hh = 0; hh < 4; hh++) {
                    ulonglong2 wv = *(const ulonglong2*)(wbase + hh * NH + 128 * u);
#pragma unroll
                    for (int bb = 0; bb < 8; bb++) {
                        FMA2(acc[bb * 4 + hh], p0[bb], wv.x);
                        FMA2(acc[bb * 4 + hh], p1[bb], wv.y);
                    }
                }
#pragma unroll
                for (int bb = 0; bb < 8; bb++) s[bb] = sn[bb];
            }

            float a[32];
#pragma unroll
            for (int i = 0; i < 32; i++) {
                u32 lo, hi;
                UNPK2(lo, hi, acc[i]);
                a[i] = __uint_as_float(lo) + __uint_as_float(hi);
            }
            RSTAGE(16, 16)
            RSTAGE(8, 8)
            RSTAGE(4, 4)
            RSTAGE(2, 2)
            RSTAGE(1, 1)
            float rec = a[0];

            hs  = D_SYN * hs + rec;
            psc = D_SYN * psc + hs;
        }

        // ---- GLIF3 neuron update (uses Iv = I_ext(t)) ----
        float I = Iv + psc;
        a0 *= D_A0;
        a1 *= D_A1;
        v = v + ((V_RST - v) * (1.0f / 20.0f) + (I + a0 + a1) * 0.5f);
        bool in_ref = ref > 0.0f;
        if (in_ref) v = V_RST;
        float spike = (!in_ref && v >= V_TH) ? 1.0f : 0.0f;
        unsigned short s16;
        if (spike > 0.0f) {
            v = V_RST; a0 += 1.0f; a1 -= 2.0f; ref = 2.0f; cnt++;
            s16 = 0x3F80;
        } else {
            ref = fmaxf(ref - 1.0f, 0.0f);
            s16 = 0;
        }
        g_spk16[t & 1][b * NH + h] = s16;

        // ---- ensure x(t+1) staged, then barrier arrive ----
        if (more) CP_WAIT(1); else CP_WAIT(0);
        __syncthreads();
        if (threadIdx.x == 0) {
            __threadfence();
            atomicAdd(&g_bar, 1u);
        }

        // ---- compute I_ext(t+1) slice while the barrier propagates ----
        if (t + 1 < T_STEPS) {
            const float* xr = xs + ((t + 1) & 1) * XBUF + b * XROW;
            float acc = 0.f;
#pragma unroll 8
            for (int k4 = 0; k4 < NI / 4; k4++) {
                float4 xv = *(const float4*)(xr + k4 * 4);
                float4 wv = *(const float4*)(wirow + k4 * 4);
                acc += xv.x * wv.x;
                acc += xv.y * wv.y;
                acc += xv.z * wv.z;
                acc += xv.w * wv.w;
            }
            Iv = acc;
        }

        // ---- barrier poll ----
        if (threadIdx.x == 0) {
            const unsigned target = (unsigned)(t + 1) * NBLK;
            unsigned cur;
            do {
                asm volatile("ld.global.acquire.gpu.u32 %0, [%1];"
                             : "=r"(cur) : "l"(&g_bar));
            } while (cur < target);
        }
        __syncthreads();
    }
    g_rate[b * NH + h] = (float)cnt * 0.001f;
}

// -------- Phase C: out[b,o] = rate[b,:] . W_out[o,:] --------
__global__ __launch_bounds__(256) void out_kernel(const float* __restrict__ Wout,
                                                  float* __restrict__ out) {
    int gw   = (blockIdx.x * blockDim.x + threadIdx.x) >> 5;
    int lane = threadIdx.x & 31;
    int b = gw >> 8;
    int o = gw & 255;
    const float* r = &g_rate[b * NH];
    const float* wp = &Wout[(size_t)o * NH];
    float s = 0.f;
    for (int hh = lane; hh < NH; hh += 32) s += r[hh] * wp[hh];
#pragma unroll
    for (int off = 16; off; off >>= 1) s += __shfl_down_sync(0xffffffffu, s, off);
    if (lane == 0) out[b * NO + o] = s;
}

// -------- launch --------
extern "C" void kernel_launch(void* const* d_in, const int* in_sizes, int n_in,
                              void* d_out, int out_size) {
    const float* x = nullptr;
    const float* W_in = nullptr;
    const float* W_rec = nullptr;
    const float* W_out = nullptr;
    for (int i = 0; i < n_in; i++) {
        switch (in_sizes[i]) {
            case T_STEPS * BATCH * NI: x     = (const float*)d_in[i]; break;
            case NH * NI:              W_in  = (const float*)d_in[i]; break;
            case NH * NH:              W_rec = (const float*)d_in[i]; break;
            case NO * NH:              W_out = (const float*)d_in[i]; break;
        }
    }
    float* out = (float*)d_out;

    cudaFuncSetAttribute(scan_kernel,
                         cudaFuncAttributeMaxDynamicSharedMemorySize, SMEM_BYTES);

    // my launch idx:  0      1..3 (dummies so scan lands on global ncu idx 5)
    init_kernel<<<1, 32>>>();
    init_kernel<<<1, 32>>>();
    init_kernel<<<1, 32>>>();
    init_kernel<<<1, 32>>>();

    // my idx 4 (global ~5): the fused persistent scan
    scan_kernel<<<NBLK, 256, SMEM_BYTES>>>(x, W_in, W_rec);

    out_kernel<<<(BATCH * NO * 32) / 256, 256>>>(W_out, out);
}

// round 11
// speedup vs baseline: 1.4152x; 1.4152x over previous
#include <cuda_runtime.h>
#include <cstdint>

// MinimalRSNN: GLIF3 + AlphaPSC recurrent SNN.
//   Phase A: I_ext = x @ W_in^T  (fp32 SGEMM, 128x128x8, f32x2 FMA) [R4-exact]
//   Phase B: persistent 1000-step scan, 128 CTAs x 512 threads
//            - 16 warps/CTA (4/SMSP) for latency hiding
//            - warp tile 4b x 4h, lanes ln/ln+16 duplicate one neuron
//            - bf16 spike transport, f32x2 accumulators, K-split 32
//   Phase C: out = spike_rate @ W_out^T
// Launch order puts scan at overall index 5 (harness poison kernel = idx 0)
// so ncu -s 5 -c 1 captures the scan.

#define T_STEPS 1000
#define BATCH   32
#define NI      512
#define NH      1024
#define NO      256

#define V_TH   (-45.0f)
#define V_RST  (-60.0f)
#define D_SYN  0.8187307530779818f
#define D_A0   0.9048374180359595f
#define D_A1   0.8187307530779818f

#define NBLK   128

#define FMA2(d, a, b)  asm("fma.rn.f32x2 %0, %1, %2, %0;" : "+l"(d) : "l"(a), "l"(b))
#define PACK2(d, lo, hi) asm("mov.b64 %0, {%1, %2};" : "=l"(d) : "r"(lo), "r"(hi))
#define UNPK2(lo, hi, s) asm("mov.b64 {%0, %1}, %2;" : "=r"(lo), "=r"(hi) : "l"(s))

typedef unsigned long long u64;
typedef unsigned int       u32;

// -------- device scratch (no allocations allowed) --------
__device__ float          g_Iext[(size_t)T_STEPS * BATCH * NH];   // 131 MB
__device__ unsigned short g_spk16[2][BATCH * NH];                 // bf16 spikes
__device__ float          g_rate[BATCH * NH];
__device__ unsigned int   g_bar;

__global__ void init_kernel() { if (threadIdx.x == 0) g_bar = 0u; }

// -------- Phase A: C[M,N] = A[M,K] * B[N,K]^T (fp32, f32x2 inner) --------
#define BM 128
#define BN 128
#define BK 8
__global__ __launch_bounds__(256, 2) void gemm_in_kernel(const float* __restrict__ A,
                                                         const float* __restrict__ Bm) {
    __shared__ float As[BK][BM];
    __shared__ float Bs[BK][BN];
    const int tid = threadIdx.x;
    const int m0 = blockIdx.y * BM, n0 = blockIdx.x * BN;
    const int lr = tid >> 1;
    const int lc = (tid & 1) * 4;
    const int tx = tid & 15, ty = tid >> 4;
    u64 acc[8][4];
#pragma unroll
    for (int i = 0; i < 8; i++)
#pragma unroll
        for (int j = 0; j < 4; j++) acc[i][j] = 0ull;

    for (int kc = 0; kc < NI; kc += BK) {
        float4 av = *(const float4*)&A [(size_t)(m0 + lr) * NI + kc + lc];
        float4 bv = *(const float4*)&Bm[(size_t)(n0 + lr) * NI + kc + lc];
        As[lc + 0][lr] = av.x; As[lc + 1][lr] = av.y;
        As[lc + 2][lr] = av.z; As[lc + 3][lr] = av.w;
        Bs[lc + 0][lr] = bv.x; Bs[lc + 1][lr] = bv.y;
        Bs[lc + 2][lr] = bv.z; Bs[lc + 3][lr] = bv.w;
        __syncthreads();
#pragma unroll
        for (int k = 0; k < BK; k++) {
            float4 a0 = *(const float4*)&As[k][ty * 8];
            float4 a1 = *(const float4*)&As[k][ty * 8 + 4];
            ulonglong2 bp = *(const ulonglong2*)&Bs[k][tx * 8];
            ulonglong2 bq = *(const ulonglong2*)&Bs[k][tx * 8 + 4];
            float aa[8] = {a0.x, a0.y, a0.z, a0.w, a1.x, a1.y, a1.z, a1.w};
            u64 ap[8];
#pragma unroll
            for (int i = 0; i < 8; i++) {
                u32 ab = __float_as_uint(aa[i]);
                PACK2(ap[i], ab, ab);
            }
#pragma unroll
            for (int i = 0; i < 8; i++) {
                FMA2(acc[i][0], ap[i], bp.x);
                FMA2(acc[i][1], ap[i], bp.y);
                FMA2(acc[i][2], ap[i], bq.x);
                FMA2(acc[i][3], ap[i], bq.y);
            }
        }
        __syncthreads();
    }
#pragma unroll
    for (int i = 0; i < 8; i++) {
        float o[8];
#pragma unroll
        for (int j = 0; j < 4; j++) {
            u32 lo, hi;
            UNPK2(lo, hi, acc[i][j]);
            o[2 * j]     = __uint_as_float(lo);
            o[2 * j + 1] = __uint_as_float(hi);
        }
        float4 o0 = {o[0], o[1], o[2], o[3]};
        float4 o1 = {o[4], o[5], o[6], o[7]};
        float* dst = &g_Iext[(size_t)(m0 + ty * 8 + i) * NH + n0 + tx * 8];
        *(float4*)dst = o0;
        *(float4*)(dst + 4) = o1;
    }
}

// -------- grid barrier (128 CTAs, 1 CTA/SM -> co-resident) --------
__device__ __forceinline__ void grid_sync(int step) {
    __syncthreads();
    if (threadIdx.x == 0) {
        __threadfence();
        atomicAdd(&g_bar, 1u);
        const unsigned target = (unsigned)(step + 1) * NBLK;
        unsigned cur;
        do {
            asm volatile("ld.global.acquire.gpu.u32 %0, [%1];" : "=r"(cur) : "l"(&g_bar));
        } while (cur < target);
    }
    __syncthreads();
}

#define RSTAGE(M, NHALF)                                                        \
    if (ln & (M)) {                                                             \
        _Pragma("unroll")                                                       \
        for (int i = 0; i < (NHALF); i++) {                                     \
            float tmp = a[i]; a[i] = a[i + (NHALF)]; a[i + (NHALF)] = tmp;      \
        }                                                                       \
    }                                                                           \
    _Pragma("unroll")                                                           \
    for (int i = 0; i < (NHALF); i++)                                           \
        a[i] += __shfl_xor_sync(0xffffffffu, a[i + (NHALF)], (M));

// -------- Phase B: persistent scan, 512 threads, warp tile 4b x 4h --------
__global__ __launch_bounds__(512, 1) void scan_kernel(const float* __restrict__ Wrec) {
    __shared__ float wt[8 * NH];       // 32 KB: this CTA's 8 W_rec rows

    const int tid = threadIdx.x;
    const int w  = tid >> 5;           // 0..15
    const int ln = tid & 31;
    const int c  = blockIdx.x;
    const int h0 = c * 8;
    const int bg = w >> 1;             // 0..7 -> batches [4bg, 4bg+4)
    const int hg = w & 1;              // h rows [4hg, 4hg+4) of slice

    // preload weights (2048 float4 across 512 threads)
    {
        const float4* src = (const float4*)(Wrec + (size_t)h0 * NH);
#pragma unroll
        for (int i = 0; i < 4; i++)
            ((float4*)wt)[tid + i * 512] = src[tid + i * 512];
    }
    __syncthreads();

    // neuron ownership: lanes ln and ln^16 duplicate output o = ln & 15
    const int o  = ln & 15;
    const int b  = 4 * bg + (o >> 2);
    const int h  = h0 + 4 * hg + (o & 3);
    const float* wbase = wt + (4 * hg) * NH + 4 * ln;   // + hh*NH + 128*u

    float v = V_RST, a0 = 0.f, a1 = 0.f, ref = 0.f, hs = 0.f, psc = 0.f;
    int cnt = 0;
    float Iv = __ldcg(&g_Iext[(size_t)b * NH + h]);

    for (int t = 0; t < T_STEPS; t++) {
        if (t > 0) {
            const char* sp = (const char*)g_spk16[(t - 1) & 1];
            u64 acc[16];
#pragma unroll
            for (int i = 0; i < 16; i++) acc[i] = 0ull;

            // lane k-slice: bf16 byte offset 8*ln + 256*u within each batch row
            uint2 s[4], sn[4];
#pragma unroll
            for (int bb = 0; bb < 4; bb++)
                s[bb] = __ldcg((const uint2*)(sp + (4 * bg + bb) * (NH * 2) + 8 * ln));

#pragma unroll
            for (int u = 0; u < 8; u++) {
                if (u < 7) {
#pragma unroll
                    for (int bb = 0; bb < 4; bb++)
                        sn[bb] = __ldcg((const uint2*)(sp + (4 * bg + bb) * (NH * 2)
                                                          + 8 * ln + 256 * (u + 1)));
                }
                u64 p0[4], p1[4];
#pragma unroll
                for (int bb = 0; bb < 4; bb++) {
                    PACK2(p0[bb], s[bb].x << 16, s[bb].x & 0xFFFF0000u);
                    PACK2(p1[bb], s[bb].y << 16, s[bb].y & 0xFFFF0000u);
                }
#pragma unroll
                for (int hh = 0; hh < 4; hh++) {
                    ulonglong2 wv = *(const ulonglong2*)(wbase + hh * NH + 128 * u);
#pragma unroll
                    for (int bb = 0; bb < 4; bb++) {
                        FMA2(acc[bb * 4 + hh], p0[bb], wv.x);
                        FMA2(acc[bb * 4 + hh], p1[bb], wv.y);
                    }
                }
#pragma unroll
                for (int bb = 0; bb < 4; bb++) s[bb] = sn[bb];
            }

            // fold k-parity halves -> 16 partials per lane
            float a[16];
#pragma unroll
            for (int i = 0; i < 16; i++) {
                u32 lo, hi;
                UNPK2(lo, hi, acc[i]);
                a[i] = __uint_as_float(lo) + __uint_as_float(hi);
            }
            // stage 16: both halves hold the same outputs in the same order
#pragma unroll
            for (int i = 0; i < 16; i++)
                a[i] += __shfl_xor_sync(0xffffffffu, a[i], 16);
            RSTAGE(8, 8)
            RSTAGE(4, 4)
            RSTAGE(2, 2)
            RSTAGE(1, 1)
            float rec = a[0];            // lane ln: output (ln & 15)

            hs  = D_SYN * hs + rec;
            psc = D_SYN * psc + hs;
        }

        // GLIF3 neuron update (duplicated in lane pairs -> identical results)
        float I = Iv + psc;
        a0 *= D_A0;
        a1 *= D_A1;
        v = v + ((V_RST - v) * (1.0f / 20.0f) + (I + a0 + a1) * 0.5f);
        bool in_ref = ref > 0.0f;
        if (in_ref) v = V_RST;
        float spike = (!in_ref && v >= V_TH) ? 1.0f : 0.0f;
        unsigned short s16;
        if (spike > 0.0f) {
            v = V_RST; a0 += 1.0f; a1 -= 2.0f; ref = 2.0f; cnt++;
            s16 = 0x3F80;
        } else {
            ref = fmaxf(ref - 1.0f, 0.0f);
            s16 = 0;
        }
        g_spk16[t & 1][b * NH + h] = s16;   // duplicate lanes write same value

        int tn = (t < T_STEPS - 1) ? t + 1 : t;
        Iv = __ldcg(&g_Iext[((size_t)tn * BATCH + b) * NH + h]);

        grid_sync(t);
    }
    g_rate[b * NH + h] = (float)cnt * 0.001f;
}

// -------- Phase C --------
__global__ __launch_bounds__(256) void out_kernel(const float* __restrict__ Wout,
                                                  float* __restrict__ out) {
    int gw   = (blockIdx.x * blockDim.x + threadIdx.x) >> 5;
    int lane = threadIdx.x & 31;
    int b = gw >> 8;
    int o = gw & 255;
    const float* r = &g_rate[b * NH];
    const float* wp = &Wout[(size_t)o * NH];
    float s = 0.f;
    for (int hh = lane; hh < NH; hh += 32) s += r[hh] * wp[hh];
#pragma unroll
    for (int off = 16; off; off >>= 1) s += __shfl_down_sync(0xffffffffu, s, off);
    if (lane == 0) out[b * NO + o] = s;
}

// -------- launch --------
extern "C" void kernel_launch(void* const* d_in, const int* in_sizes, int n_in,
                              void* d_out, int out_size) {
    const float* x = nullptr;
    const float* W_in = nullptr;
    const float* W_rec = nullptr;
    const float* W_out = nullptr;
    for (int i = 0; i < n_in; i++) {
        switch (in_sizes[i]) {
            case T_STEPS * BATCH * NI: x     = (const float*)d_in[i]; break;
            case NH * NI:              W_in  = (const float*)d_in[i]; break;
            case NH * NH:              W_rec = (const float*)d_in[i]; break;
            case NO * NH:              W_out = (const float*)d_in[i]; break;
        }
    }
    float* out = (float*)d_out;

    // harness poison kernel is overall launch idx 0; mine start at 1.
    init_kernel<<<1, 32>>>();                    // overall 1

    dim3 g1(NH / BN, (T_STEPS * BATCH) / BM);    // (8, 250)
    gemm_in_kernel<<<g1, 256>>>(x, W_in);        // overall 2

    init_kernel<<<1, 32>>>();                    // overall 3
    init_kernel<<<1, 32>>>();                    // overall 4

    scan_kernel<<<NBLK, 512>>>(W_rec);           // overall 5  <- ncu -s 5 -c 1

    out_kernel<<<(BATCH * NO * 32) / 256, 256>>>(W_out, out);
}